// round 1
// baseline (speedup 1.0000x reference)
#include <cuda_runtime.h>

// Problem constants (fixed by setup_inputs: B=32, NT=32, NP=8192)
#define SLABS 1024                 // B*NT
#define F4_PER_SLAB 6144           // 8192 points * 3 floats / 4
#define XTHREADS 256
#define F4_PER_THREAD 3            // 4 points per thread
#define BLOCKS_PER_SLAB 8          // 6144 / (256*3)

// Per-(b,t) rotation (row-major 9) + translation (3). 48 KB scratch.
__device__ float g_RT[SLABS * 12];

__global__ void rt_kernel(const float* __restrict__ dof) {
    int i = blockIdx.x * blockDim.x + threadIdx.x;
    if (i >= SLABS) return;
    const float* d = dof + i * 6;
    float vx = d[0], vy = d[1], vz = d[2];
    float wx = d[3], wy = d[4], wz = d[5];
    float t2 = wx*wx + wy*wy + wz*wz;
    float t  = sqrtf(t2);
    float A, B, C;
    if (t < 1e-4f) {
        A = 1.0f - t2 * (1.0f/6.0f);
        B = 0.5f - t2 * (1.0f/24.0f);
        C = (1.0f/6.0f) - t2 * (1.0f/120.0f);
    } else {
        float s, c;
        sincosf(t, &s, &c);
        A = s / t;
        B = (1.0f - c) / t2;
        C = (t - s) / (t2 * t);
    }
    // K^2 = w w^T - t2 * I  =>  R = I + A*K + B*(wwT - t2 I), V = I + B*K + C*(wwT - t2 I)
    float r00 = 1.0f + B*(wx*wx - t2);
    float r01 = -A*wz + B*wx*wy;
    float r02 =  A*wy + B*wx*wz;
    float r10 =  A*wz + B*wx*wy;
    float r11 = 1.0f + B*(wy*wy - t2);
    float r12 = -A*wx + B*wy*wz;
    float r20 = -A*wy + B*wx*wz;
    float r21 =  A*wx + B*wy*wz;
    float r22 = 1.0f + B*(wz*wz - t2);

    float v00 = 1.0f + C*(wx*wx - t2);
    float v01 = -B*wz + C*wx*wy;
    float v02 =  B*wy + C*wx*wz;
    float v10 =  B*wz + C*wx*wy;
    float v11 = 1.0f + C*(wy*wy - t2);
    float v12 = -B*wx + C*wy*wz;
    float v20 = -B*wy + C*wx*wz;
    float v21 =  B*wx + C*wy*wz;
    float v22 = 1.0f + C*(wz*wz - t2);

    float tx = v00*vx + v01*vy + v02*vz;
    float ty = v10*vx + v11*vy + v12*vz;
    float tz = v20*vx + v21*vy + v22*vz;

    float* o = g_RT + i * 12;
    o[0]=r00; o[1]=r01; o[2]=r02;
    o[3]=r10; o[4]=r11; o[5]=r12;
    o[6]=r20; o[7]=r21; o[8]=r22;
    o[9]=tx;  o[10]=ty; o[11]=tz;
}

__global__ __launch_bounds__(XTHREADS) void xform_kernel(
    const float4* __restrict__ X, float4* __restrict__ out)
{
    int blk  = blockIdx.x;
    int slab = blk >> 3;          // / BLOCKS_PER_SLAB
    int loc  = blk & 7;

    const float* rt = g_RT + slab * 12;
    float r00 = rt[0], r01 = rt[1], r02 = rt[2];
    float r10 = rt[3], r11 = rt[4], r12 = rt[5];
    float r20 = rt[6], r21 = rt[7], r22 = rt[8];
    float tx  = rt[9], ty = rt[10], tz = rt[11];

    long base = (long)slab * F4_PER_SLAB
              + (long)loc * (XTHREADS * F4_PER_THREAD)
              + (long)threadIdx.x * F4_PER_THREAD;

    float4 a = X[base];
    float4 b = X[base + 1];
    float4 c = X[base + 2];

    // 4 points packed across 3 float4s:
    // p0=(a.x,a.y,a.z) p1=(a.w,b.x,b.y) p2=(b.z,b.w,c.x) p3=(c.y,c.z,c.w)
    float ox0 = fmaf(r00, a.x, fmaf(r01, a.y, fmaf(r02, a.z, tx)));
    float oy0 = fmaf(r10, a.x, fmaf(r11, a.y, fmaf(r12, a.z, ty)));
    float oz0 = fmaf(r20, a.x, fmaf(r21, a.y, fmaf(r22, a.z, tz)));

    float ox1 = fmaf(r00, a.w, fmaf(r01, b.x, fmaf(r02, b.y, tx)));
    float oy1 = fmaf(r10, a.w, fmaf(r11, b.x, fmaf(r12, b.y, ty)));
    float oz1 = fmaf(r20, a.w, fmaf(r21, b.x, fmaf(r22, b.y, tz)));

    float ox2 = fmaf(r00, b.z, fmaf(r01, b.w, fmaf(r02, c.x, tx)));
    float oy2 = fmaf(r10, b.z, fmaf(r11, b.w, fmaf(r12, c.x, ty)));
    float oz2 = fmaf(r20, b.z, fmaf(r21, b.w, fmaf(r22, c.x, tz)));

    float ox3 = fmaf(r00, c.y, fmaf(r01, c.z, fmaf(r02, c.w, tx)));
    float oy3 = fmaf(r10, c.y, fmaf(r11, c.z, fmaf(r12, c.w, ty)));
    float oz3 = fmaf(r20, c.y, fmaf(r21, c.z, fmaf(r22, c.w, tz)));

    out[base]     = make_float4(ox0, oy0, oz0, ox1);
    out[base + 1] = make_float4(oy1, oz1, ox2, oy2);
    out[base + 2] = make_float4(oz2, ox3, oy3, oz3);
}

extern "C" void kernel_launch(void* const* d_in, const int* in_sizes, int n_in,
                              void* d_out, int out_size) {
    const float4* X  = (const float4*)d_in[0];   // X_v: 32*32*8192*3 f32
    const float*  dof = (const float*)d_in[1];   // dof: 32*32*6 f32
    float4* out = (float4*)d_out;

    rt_kernel<<<(SLABS + 255) / 256, 256>>>(dof);
    xform_kernel<<<SLABS * BLOCKS_PER_SLAB, XTHREADS>>>(X, out);
}

// round 2
// speedup vs baseline: 1.0518x; 1.0518x over previous
#include <cuda_runtime.h>

// Problem constants (fixed by setup_inputs: B=32, NT=32, NP=8192)
#define SLABS 1024            // B*NT
#define SLAB_F4 6144          // 8192 points * 3 floats / 4
#define THREADS 256
#define TILE_F4 768           // 256 threads * 3 float4 per tile
#define TILES_PER_BLOCK 4
#define BLOCK_F4 (TILE_F4 * TILES_PER_BLOCK)   // 3072 = half a slab
#define BLOCKS_PER_SLAB 2
#define GRID (SLABS * BLOCKS_PER_SLAB)         // 2048

__global__ __launch_bounds__(THREADS) void fused_xform_kernel(
    const float4* __restrict__ X, const float* __restrict__ dof,
    float4* __restrict__ out)
{
    const int blk  = blockIdx.x;
    const int slab = blk >> 1;
    const int tid  = threadIdx.x;

    // ---- per-slab SE(3) exp, computed redundantly by every thread ----
    const float* d = dof + slab * 6;
    float vx = d[0], vy = d[1], vz = d[2];
    float wx = d[3], wy = d[4], wz = d[5];
    float t2 = wx*wx + wy*wy + wz*wz;
    float th = sqrtf(t2);
    float A, B, C;
    if (th < 1e-4f) {
        A = 1.0f - t2 * (1.0f/6.0f);
        B = 0.5f - t2 * (1.0f/24.0f);
        C = (1.0f/6.0f) - t2 * (1.0f/120.0f);
    } else {
        float s, c;
        sincosf(th, &s, &c);
        A = s / th;
        B = (1.0f - c) / t2;
        C = (th - s) / (t2 * th);
    }
    // K^2 = w w^T - t2*I  =>  R = I + A*K + B*(wwT - t2 I), V = I + B*K + C*(wwT - t2 I)
    float r00 = 1.0f + B*(wx*wx - t2);
    float r01 = -A*wz + B*wx*wy;
    float r02 =  A*wy + B*wx*wz;
    float r10 =  A*wz + B*wx*wy;
    float r11 = 1.0f + B*(wy*wy - t2);
    float r12 = -A*wx + B*wy*wz;
    float r20 = -A*wy + B*wx*wz;
    float r21 =  A*wx + B*wy*wz;
    float r22 = 1.0f + B*(wz*wz - t2);

    float v00 = 1.0f + C*(wx*wx - t2);
    float v01 = -B*wz + C*wx*wy;
    float v02 =  B*wy + C*wx*wz;
    float v10 =  B*wz + C*wx*wy;
    float v11 = 1.0f + C*(wy*wy - t2);
    float v12 = -B*wx + C*wy*wz;
    float v20 = -B*wy + C*wx*wz;
    float v21 =  B*wx + C*wy*wz;
    float v22 = 1.0f + C*(wz*wz - t2);

    float tx = v00*vx + v01*vy + v02*vz;
    float ty = v10*vx + v11*vy + v12*vz;
    float tz = v20*vx + v21*vy + v22*vz;

    // ---- SMEM-staged streaming transform ----
    __shared__ float4 s_in[TILE_F4];
    __shared__ float4 s_out[TILE_F4];

    const int base0 = slab * SLAB_F4 + (blk & 1) * BLOCK_F4;

    #pragma unroll
    for (int t = 0; t < TILES_PER_BLOCK; t++) {
        const int tb = base0 + t * TILE_F4;

        // stage-in: unit-stride across warp -> 4 lines per LDG.128
        #pragma unroll
        for (int j = 0; j < 3; j++)
            s_in[j * THREADS + tid] = X[tb + j * THREADS + tid];
        __syncthreads();

        // per-point work from SMEM (LDS.128 word-stride 12: conflict-free)
        float4 a = s_in[3 * tid + 0];
        float4 b = s_in[3 * tid + 1];
        float4 c = s_in[3 * tid + 2];

        // 4 points packed across 3 float4s:
        // p0=(a.x,a.y,a.z) p1=(a.w,b.x,b.y) p2=(b.z,b.w,c.x) p3=(c.y,c.z,c.w)
        float ox0 = fmaf(r00, a.x, fmaf(r01, a.y, fmaf(r02, a.z, tx)));
        float oy0 = fmaf(r10, a.x, fmaf(r11, a.y, fmaf(r12, a.z, ty)));
        float oz0 = fmaf(r20, a.x, fmaf(r21, a.y, fmaf(r22, a.z, tz)));

        float ox1 = fmaf(r00, a.w, fmaf(r01, b.x, fmaf(r02, b.y, tx)));
        float oy1 = fmaf(r10, a.w, fmaf(r11, b.x, fmaf(r12, b.y, ty)));
        float oz1 = fmaf(r20, a.w, fmaf(r21, b.x, fmaf(r22, b.y, tz)));

        float ox2 = fmaf(r00, b.z, fmaf(r01, b.w, fmaf(r02, c.x, tx)));
        float oy2 = fmaf(r10, b.z, fmaf(r11, b.w, fmaf(r12, c.x, ty)));
        float oz2 = fmaf(r20, b.z, fmaf(r21, b.w, fmaf(r22, c.x, tz)));

        float ox3 = fmaf(r00, c.y, fmaf(r01, c.z, fmaf(r02, c.w, tx)));
        float oy3 = fmaf(r10, c.y, fmaf(r11, c.z, fmaf(r12, c.w, ty)));
        float oz3 = fmaf(r20, c.y, fmaf(r21, c.z, fmaf(r22, c.w, tz)));

        s_out[3 * tid + 0] = make_float4(ox0, oy0, oz0, ox1);
        s_out[3 * tid + 1] = make_float4(oy1, oz1, ox2, oy2);
        s_out[3 * tid + 2] = make_float4(oz2, ox3, oy3, oz3);
        __syncthreads();

        // stage-out: unit-stride, streaming hint (don't evict input from L2)
        #pragma unroll
        for (int j = 0; j < 3; j++)
            __stcs(&out[tb + j * THREADS + tid], s_out[j * THREADS + tid]);
    }
}

extern "C" void kernel_launch(void* const* d_in, const int* in_sizes, int n_in,
                              void* d_out, int out_size) {
    const float4* X   = (const float4*)d_in[0];   // X_v: 32*32*8192*3 f32
    const float*  dof = (const float*)d_in[1];    // dof: 32*32*6 f32
    float4* out = (float4*)d_out;

    fused_xform_kernel<<<GRID, THREADS>>>(X, dof, out);
}